// round 8
// baseline (speedup 1.0000x reference)
#include <cuda_runtime.h>
#include <cstddef>

#define HIDDEN 1024
#define NHEAD  16
#define HD     64
#define BATCH  2
#define SEQ    2048
#define M_TOTAL (BATCH * SEQ)   // 4096
#define BH      (BATCH * NHEAD) // 32
#define CTX_SIZE ((size_t)BATCH * SEQ * HIDDEN)  // 4,194,304

typedef unsigned long long u64;

// Scratch: Q/K/V in [b,h,s,d] layout, plus exp-row-sums
__device__ float g_q[(size_t)BH * SEQ * HD];
__device__ float g_k[(size_t)BH * SEQ * HD];
__device__ float g_v[(size_t)BH * SEQ * HD];
__device__ float g_rsum[(size_t)BH * SEQ];

// ---------------------------------------------------------------------------
// Packed fp32x2 FMA (ptxas never auto-fuses FFMA2 from C++; PTX-only path).
// ---------------------------------------------------------------------------
__device__ __forceinline__ void fma2(u64& d, u64 a, u64 b) {
    asm("fma.rn.f32x2 %0, %1, %2, %0;" : "+l"(d) : "l"(a), "l"(b));
}
__device__ __forceinline__ float hsum(u64 v) {
    float lo, hi;
    asm("mov.b64 {%0, %1}, %2;" : "=f"(lo), "=f"(hi) : "l"(v));
    return lo + hi;
}

// FMA-only exp (MUFU would cost ~900us for 134M exps). Rel err ~1e-7.
__device__ __forceinline__ float fexp(float x) {
    float t = x * 1.4426950408889634f;
    float fi = rintf(t);
    float y = (t - fi) * 0.6931471805599453f;
    float p = 1.3888889e-3f;
    p = fmaf(p, y, 8.3333333e-3f);
    p = fmaf(p, y, 4.1666667e-2f);
    p = fmaf(p, y, 1.6666667e-1f);
    p = fmaf(p, y, 0.5f);
    p = fmaf(p, y, 1.0f);
    p = fmaf(p, y, 1.0f);
    return p * __int_as_float(((int)fi + 127) << 23);
}

// ---------------------------------------------------------------------------
__global__ void zero_rsum_kernel() {
    g_rsum[blockIdx.x * 256 + threadIdx.x] = 0.0f;
}

// ---------------------------------------------------------------------------
// K1: QKV projection.  C[m][n] = sum_k X[m][k]*W[n][k] + bias[n]
// Tile 128m x 64n, BK=32, block 256 (ty=16 x tx=16), microtile 8m x 4n.
// k-packed FFMA2: acc halves = (even-k, odd-k) partials.
// Pitch 36 floats (144B == 16 mod 128) -> strided b-loads conflict-free.
// ---------------------------------------------------------------------------
__global__ __launch_bounds__(256, 2) void qkv_kernel(
    const float* __restrict__ X,
    const float* __restrict__ Wq, const float* __restrict__ bq,
    const float* __restrict__ Wk, const float* __restrict__ bk,
    const float* __restrict__ Wv, const float* __restrict__ bv)
{
    __shared__ float As[128 * 36];   // [m][k] pitch 36
    __shared__ float Bs[64 * 36];    // [n][k] pitch 36

    const int which = blockIdx.z;
    const float* W    = (which == 0) ? Wq : (which == 1) ? Wk : Wv;
    const float* bias = (which == 0) ? bq : (which == 1) ? bk : bv;
    float* dst        = (which == 0) ? g_q : (which == 1) ? g_k : g_v;

    const int n0 = blockIdx.x * 64;      // 16 tiles
    const int m0 = blockIdx.y * 128;     // 32 tiles
    const int tid = threadIdx.x;
    const int ty = tid >> 4;             // 0..15 -> rows ty*8..+7
    const int tx = tid & 15;             // 0..15 -> cols tx+16j

    u64 acc[8][4];
    #pragma unroll
    for (int i = 0; i < 8; i++)
        #pragma unroll
        for (int j = 0; j < 4; j++) acc[i][j] = 0ull;

    for (int k0 = 0; k0 < HIDDEN; k0 += 32) {
        #pragma unroll
        for (int it = 0; it < 4; it++) {          // As: 1024 float4
            int f = tid + it * 256;
            int row = f >> 3;
            int c = (f & 7) << 2;
            *(float4*)&As[row * 36 + c] =
                *(const float4*)&X[(size_t)(m0 + row) * HIDDEN + k0 + c];
        }
        #pragma unroll
        for (int it = 0; it < 2; it++) {          // Bs: 512 float4
            int f = tid + it * 256;
            int row = f >> 3;
            int c = (f & 7) << 2;
            *(float4*)&Bs[row * 36 + c] =
                *(const float4*)&W[(size_t)(n0 + row) * HIDDEN + k0 + c];
        }
        __syncthreads();
        #pragma unroll
        for (int kk = 0; kk < 32; kk += 4) {
            ulonglong2 b2[4];
            #pragma unroll
            for (int j = 0; j < 4; j++)
                b2[j] = *(const ulonglong2*)&Bs[(tx + 16 * j) * 36 + kk];
            #pragma unroll
            for (int i = 0; i < 8; i++) {
                ulonglong2 a2 = *(const ulonglong2*)&As[(ty * 8 + i) * 36 + kk];
                #pragma unroll
                for (int j = 0; j < 4; j++) {
                    fma2(acc[i][j], a2.x, b2[j].x);
                    fma2(acc[i][j], a2.y, b2[j].y);
                }
            }
        }
        __syncthreads();
    }

    // epilogue: horizontal add + bias, scatter to [b,h,s,d]
    const int h = n0 >> 6;               // tile is 64-wide, head-aligned
    #pragma unroll
    for (int i = 0; i < 8; i++) {
        int m = m0 + ty * 8 + i;
        int batch = m >> 11;
        int s = m & 2047;
        float* base = dst + (((size_t)batch * NHEAD + h) * SEQ + s) * HD;
        #pragma unroll
        for (int j = 0; j < 4; j++) {
            int d = tx + 16 * j;
            base[d] = hsum(acc[i][j]) + bias[n0 + d];
        }
    }
}

// ---------------------------------------------------------------------------
// K2: scores.  E = exp(Q K^T / 8) unnormalized into probs region.
// Tile 128q x 128k, block 512 (warp==ty group: full-warp-broadcast a-loads,
// full-warp shfl rowsum). Microtile 8x4, k-packed FFMA2, pitch 68.
// HD=64 -> single smem stage, no k-loop.
// ---------------------------------------------------------------------------
#define SC_SMEM ((128 * 68 + 128 * 68) * 4)   // 69632 bytes

__global__ __launch_bounds__(512, 1) void scores_kernel(float* __restrict__ out)
{
    extern __shared__ float sm[];
    float* Qs = sm;              // [128 rows][68]
    float* Ks = sm + 128 * 68;   // [128 keys][68]

    const int kb = blockIdx.x;   // 0..15
    const int qb = blockIdx.y;   // 0..15
    const int bh = blockIdx.z;   // 0..31
    const int tid = threadIdx.x;
    const int ty = tid >> 5;     // warp id 0..15 -> rows ty*8..+7
    const int tx = tid & 31;     // lane -> keys tx+32j

    const float* Qp = g_q + ((size_t)bh * SEQ + qb * 128) * HD;
    const float* Kp = g_k + ((size_t)bh * SEQ + kb * 128) * HD;

    #pragma unroll
    for (int it = 0; it < 4; it++) {      // each: 2048 float4
        int f = tid + it * 512;
        int row = f >> 4;
        int c = (f & 15) << 2;
        *(float4*)&Qs[row * 68 + c] = *(const float4*)&Qp[(size_t)row * HD + c];
        *(float4*)&Ks[row * 68 + c] = *(const float4*)&Kp[(size_t)row * HD + c];
    }
    __syncthreads();

    u64 acc[8][4];
    #pragma unroll
    for (int i = 0; i < 8; i++)
        #pragma unroll
        for (int j = 0; j < 4; j++) acc[i][j] = 0ull;

    #pragma unroll
    for (int kk = 0; kk < HD; kk += 4) {
        ulonglong2 b2[4];
        #pragma unroll
        for (int j = 0; j < 4; j++)
            b2[j] = *(const ulonglong2*)&Ks[(tx + 32 * j) * 68 + kk];
        #pragma unroll
        for (int i = 0; i < 8; i++) {
            ulonglong2 a2 = *(const ulonglong2*)&Qs[(ty * 8 + i) * 68 + kk];
            #pragma unroll
            for (int j = 0; j < 4; j++) {
                fma2(acc[i][j], a2.x, b2[j].x);
                fma2(acc[i][j], a2.y, b2[j].y);
            }
        }
    }

    float* Ebase = out + CTX_SIZE + ((size_t)bh * SEQ + qb * 128) * SEQ + kb * 128;
    #pragma unroll
    for (int i = 0; i < 8; i++) {
        int row = ty * 8 + i;
        float rs = 0.0f;
        #pragma unroll
        for (int j = 0; j < 4; j++) {
            float e = fexp(hsum(acc[i][j]) * 0.125f);
            Ebase[(size_t)row * SEQ + tx + 32 * j] = e;
            rs += e;
        }
        #pragma unroll
        for (int o = 16; o > 0; o >>= 1)
            rs += __shfl_xor_sync(0xffffffffu, rs, o);
        if (tx == 0)
            atomicAdd(&g_rsum[(size_t)bh * SEQ + qb * 128 + row], rs);
    }
}

// ---------------------------------------------------------------------------
// K3: ctx = (E @ V) * rinv; normalizes probs in place while staging E.
// Tile 128 rows x 64 dims, keys streamed 64 at a time. Block 256, microtile
// 8x4, k-packed FFMA2. V staged TRANSPOSED (Vt[d][key]) so key-pairs are
// contiguous; pitch 68 keeps strided b-loads conflict-free.
// ---------------------------------------------------------------------------
#define CT_SMEM ((128 * 68 + 64 * 68) * 4)   // 52224 bytes

__global__ __launch_bounds__(256, 2) void ctx_kernel(float* __restrict__ out)
{
    extern __shared__ float sm[];
    float* Es = sm;              // [128 rows][68]
    float* Vt = sm + 128 * 68;   // [64 dims][68 keys]
    __shared__ float rinv_s[128];

    const int qb = blockIdx.x;   // 0..15
    const int bh = blockIdx.y;   // 0..31
    const int batch = bh >> 4;
    const int h = bh & 15;
    const int tid = threadIdx.x;
    const int ty = tid >> 4;     // rows ty*8..+7
    const int tx = tid & 15;     // dims tx+16j

    if (tid < 128)
        rinv_s[tid] = 1.0f / g_rsum[(size_t)bh * SEQ + qb * 128 + tid];

    float* Erow = out + CTX_SIZE + ((size_t)bh * SEQ + qb * 128) * SEQ;
    const float* Vp = g_v + (size_t)bh * SEQ * HD;

    u64 acc[8][4];
    #pragma unroll
    for (int i = 0; i < 8; i++)
        #pragma unroll
        for (int j = 0; j < 4; j++) acc[i][j] = 0ull;

    for (int k0 = 0; k0 < SEQ; k0 += 64) {
        __syncthreads();   // covers rinv_s on first iter, smem reuse after
        // V tile transposed: 64 keys x 64 dims
        #pragma unroll
        for (int it = 0; it < 4; it++) {
            int f = tid + it * 256;
            int key = f >> 4;
            int c = (f & 15) << 2;
            float4 v = *(const float4*)&Vp[(size_t)(k0 + key) * HD + c];
            Vt[(c + 0) * 68 + key] = v.x; Vt[(c + 1) * 68 + key] = v.y;
            Vt[(c + 2) * 68 + key] = v.z; Vt[(c + 3) * 68 + key] = v.w;
        }
        // E tile: normalize, write probs back, stage row-major
        #pragma unroll
        for (int it = 0; it < 8; it++) {
            int f = tid + it * 256;
            int row = f >> 4;
            int kc = (f & 15) << 2;
            float ri = rinv_s[row];
            float4 v = *(const float4*)&Erow[(size_t)row * SEQ + k0 + kc];
            v.x *= ri; v.y *= ri; v.z *= ri; v.w *= ri;
            *(float4*)&Erow[(size_t)row * SEQ + k0 + kc] = v;
            *(float4*)&Es[row * 68 + kc] = v;
        }
        __syncthreads();

        #pragma unroll
        for (int kk = 0; kk < 64; kk += 4) {
            ulonglong2 b2[4];
            #pragma unroll
            for (int j = 0; j < 4; j++)
                b2[j] = *(const ulonglong2*)&Vt[(tx + 16 * j) * 68 + kk];
            #pragma unroll
            for (int i = 0; i < 8; i++) {
                ulonglong2 a2 = *(const ulonglong2*)&Es[(ty * 8 + i) * 68 + kk];
                #pragma unroll
                for (int j = 0; j < 4; j++) {
                    fma2(acc[i][j], a2.x, b2[j].x);
                    fma2(acc[i][j], a2.y, b2[j].y);
                }
            }
        }
    }

    // ctx out [b][s][h*64+d]
    #pragma unroll
    for (int i = 0; i < 8; i++) {
        int s = qb * 128 + ty * 8 + i;
        float* p = out + ((size_t)batch * SEQ + s) * HIDDEN + h * HD;
        #pragma unroll
        for (int j = 0; j < 4; j++)
            p[tx + 16 * j] = hsum(acc[i][j]);
    }
}

// ---------------------------------------------------------------------------
extern "C" void kernel_launch(void* const* d_in, const int* in_sizes, int n_in,
                              void* d_out, int out_size)
{
    const float* X  = (const float*)d_in[0];
    const float* Wq = (const float*)d_in[1];
    const float* bq = (const float*)d_in[2];
    const float* Wk = (const float*)d_in[3];
    const float* bk = (const float*)d_in[4];
    const float* Wv = (const float*)d_in[5];
    const float* bv = (const float*)d_in[6];
    float* out = (float*)d_out;

    zero_rsum_kernel<<<BH * SEQ / 256, 256>>>();

    dim3 g1(HIDDEN / 64, M_TOTAL / 128, 3);
    qkv_kernel<<<g1, 256>>>(X, Wq, bq, Wk, bk, Wv, bv);

    cudaFuncSetAttribute(scores_kernel,
                         cudaFuncAttributeMaxDynamicSharedMemorySize, SC_SMEM);
    dim3 g2(SEQ / 128, SEQ / 128, BH);
    scores_kernel<<<g2, 512, SC_SMEM>>>(out);

    cudaFuncSetAttribute(ctx_kernel,
                         cudaFuncAttributeMaxDynamicSharedMemorySize, CT_SMEM);
    dim3 g3(SEQ / 128, BH);
    ctx_kernel<<<g3, 256, CT_SMEM>>>(out);
}

// round 9
// speedup vs baseline: 1.0319x; 1.0319x over previous
#include <cuda_runtime.h>
#include <cstddef>

#define HIDDEN 1024
#define NHEAD  16
#define HD     64
#define BATCH  2
#define SEQ    2048
#define M_TOTAL (BATCH * SEQ)   // 4096
#define BH      (BATCH * NHEAD) // 32
#define CTX_SIZE ((size_t)BATCH * SEQ * HIDDEN)  // 4,194,304

typedef unsigned long long u64;

__device__ float g_q[(size_t)BH * SEQ * HD];
__device__ float g_k[(size_t)BH * SEQ * HD];
__device__ float g_v[(size_t)BH * SEQ * HD];
__device__ float g_rsum[(size_t)BH * SEQ];

// ---------------------------------------------------------------------------
// Packed fp32x2 helpers (PTX-only path; ptxas never auto-fuses FFMA2).
// ---------------------------------------------------------------------------
__device__ __forceinline__ void fma2(u64& d, u64 a, u64 b) {
    asm("fma.rn.f32x2 %0, %1, %2, %0;" : "+l"(d) : "l"(a), "l"(b));
}
__device__ __forceinline__ u64 pack2(float a) {           // (a, a)
    u64 r;
    asm("mov.b64 %0, {%1, %1};" : "=l"(r) : "f"(a));
    return r;
}
__device__ __forceinline__ void unpack2(u64 v, float& lo, float& hi) {
    asm("mov.b64 {%0, %1}, %2;" : "=f"(lo), "=f"(hi) : "l"(v));
}
__device__ __forceinline__ float hsum(u64 v) {
    float lo, hi; unpack2(v, lo, hi); return lo + hi;
}

// cp.async 16B (LDGSTS)
__device__ __forceinline__ void cpa16(unsigned sm, const void* g) {
    asm volatile("cp.async.cg.shared.global [%0], [%1], 16;" :: "r"(sm), "l"(g));
}
#define CPA_COMMIT() asm volatile("cp.async.commit_group;")
#define CPA_WAIT1()  asm volatile("cp.async.wait_group 1;")
#define CPA_WAIT0()  asm volatile("cp.async.wait_group 0;")

// FMA-only exp (MUFU would cost ~900us for 134M exps). Rel err ~1e-7.
__device__ __forceinline__ float fexp(float x) {
    float t = x * 1.4426950408889634f;
    float fi = rintf(t);
    float y = (t - fi) * 0.6931471805599453f;
    float p = 1.3888889e-3f;
    p = fmaf(p, y, 8.3333333e-3f);
    p = fmaf(p, y, 4.1666667e-2f);
    p = fmaf(p, y, 1.6666667e-1f);
    p = fmaf(p, y, 0.5f);
    p = fmaf(p, y, 1.0f);
    p = fmaf(p, y, 1.0f);
    return p * __int_as_float(((int)fi + 127) << 23);
}

// ---------------------------------------------------------------------------
__global__ void zero_rsum_kernel() {
    g_rsum[blockIdx.x * 256 + threadIdx.x] = 0.0f;
}

// ---------------------------------------------------------------------------
// K1: QKV projection.  Tile 128m x 32n, BK=32, block 256 (ty16 x tx16),
// microtile 8m x 2n, k-paired FFMA2 (acc halves = even/odd k partials).
// Double-buffered cp.async; static smem (46080 B) -> 3 CTAs/SM.
// ---------------------------------------------------------------------------
#define QA 4608   // 128*36
#define QB 1152   // 32*36

__global__ __launch_bounds__(256, 3) void qkv_kernel(
    const float* __restrict__ X,
    const float* __restrict__ Wq, const float* __restrict__ bq,
    const float* __restrict__ Wk, const float* __restrict__ bk,
    const float* __restrict__ Wv, const float* __restrict__ bv)
{
    __shared__ float smbuf[2 * QA + 2 * QB];
    const unsigned smb = (unsigned)__cvta_generic_to_shared(smbuf);

    const int which = blockIdx.z;
    const float* W    = (which == 0) ? Wq : (which == 1) ? Wk : Wv;
    const float* bias = (which == 0) ? bq : (which == 1) ? bk : bv;
    float* dst        = (which == 0) ? g_q : (which == 1) ? g_k : g_v;

    const int n0 = blockIdx.x * 32;
    const int m0 = blockIdx.y * 128;
    const int tid = threadIdx.x;
    const int ty = tid >> 4;
    const int tx = tid & 15;

    u64 acc[8][2];
    #pragma unroll
    for (int i = 0; i < 8; i++) { acc[i][0] = 0ull; acc[i][1] = 0ull; }

    // stage loader
    auto load_stage = [&](int s, int k0) {
        unsigned As = smb + (unsigned)(s * QA) * 4u;
        unsigned Bs = smb + (unsigned)(2 * QA + s * QB) * 4u;
        #pragma unroll
        for (int it = 0; it < 4; it++) {            // As: 1024 float4
            int f = tid + it * 256;
            int row = f >> 3;
            int c = (f & 7) << 2;
            cpa16(As + (unsigned)(row * 36 + c) * 4u,
                  &X[(size_t)(m0 + row) * HIDDEN + k0 + c]);
        }
        {                                           // Bs: 256 float4
            int row = tid >> 3;
            int c = (tid & 7) << 2;
            cpa16(Bs + (unsigned)(row * 36 + c) * 4u,
                  &W[(size_t)(n0 + row) * HIDDEN + k0 + c]);
        }
    };

    load_stage(0, 0);
    CPA_COMMIT();

    const float* Asf = smbuf;
    const float* Bsf = smbuf + 2 * QA;

    for (int i = 0; i < 32; i++) {
        if (i < 31) { load_stage((i + 1) & 1, (i + 1) * 32); CPA_COMMIT(); CPA_WAIT1(); }
        else        { CPA_WAIT0(); }
        __syncthreads();

        const float* As = Asf + (i & 1) * QA;
        const float* Bs = Bsf + (i & 1) * QB;
        #pragma unroll
        for (int kk = 0; kk < 32; kk += 4) {
            ulonglong2 b0 = *(const ulonglong2*)&Bs[tx * 36 + kk];
            ulonglong2 b1 = *(const ulonglong2*)&Bs[(tx + 16) * 36 + kk];
            #pragma unroll
            for (int r = 0; r < 8; r++) {
                ulonglong2 a2 = *(const ulonglong2*)&As[(ty * 8 + r) * 36 + kk];
                fma2(acc[r][0], a2.x, b0.x); fma2(acc[r][0], a2.y, b0.y);
                fma2(acc[r][1], a2.x, b1.x); fma2(acc[r][1], a2.y, b1.y);
            }
        }
        __syncthreads();
    }

    const int h = n0 >> 6;
    #pragma unroll
    for (int r = 0; r < 8; r++) {
        int m = m0 + ty * 8 + r;
        int batch = m >> 11;
        int s = m & 2047;
        float* base = dst + (((size_t)batch * NHEAD + h) * SEQ + s) * HD;
        int d0 = (n0 & 63) + tx;
        base[d0]      = hsum(acc[r][0]) + bias[n0 + tx];
        base[d0 + 16] = hsum(acc[r][1]) + bias[n0 + tx + 16];
    }
}

// ---------------------------------------------------------------------------
// K2: scores.  E = exp(QK^T/8) unnormalized -> probs region; rsum atomics.
// Tile 128q x 64k, block 256, microtile 8q x 4k as key-PAIRED FFMA2
// (acc[8][2] u64, 32 regs, no hsum). K staged transposed Kt[d][key] so key
// pairs are contiguous; Q natural for scalar broadcast a-loads.
// ---------------------------------------------------------------------------
#define SC_SMEM ((128 * 68 + 64 * 68) * 4)   // 52224 B

__global__ __launch_bounds__(256, 3) void scores_kernel(float* __restrict__ out)
{
    extern __shared__ float sm[];
    float* Qs = sm;              // [128 rows][68]
    float* Kt = sm + 128 * 68;   // [64 d][68 keys]

    const int kb = blockIdx.x;   // 0..31 (64-key tiles)
    const int qb = blockIdx.y;   // 0..15
    const int bh = blockIdx.z;   // 0..31
    const int tid = threadIdx.x;
    const int ty = tid >> 4;
    const int tx = tid & 15;

    const float* Qp = g_q + ((size_t)bh * SEQ + qb * 128) * HD;
    const float* Kp = g_k + ((size_t)bh * SEQ + kb * 64) * HD;

    #pragma unroll
    for (int it = 0; it < 8; it++) {      // Q: 2048 float4
        int f = tid + it * 256;
        int row = f >> 4;
        int c = (f & 15) << 2;
        *(float4*)&Qs[row * 68 + c] = *(const float4*)&Qp[(size_t)row * HD + c];
    }
    #pragma unroll
    for (int it = 0; it < 4; it++) {      // K: 1024 float4, transposed store
        int f = tid + it * 256;
        int key = f >> 4;
        int c = (f & 15) << 2;
        float4 v = *(const float4*)&Kp[(size_t)key * HD + c];
        Kt[(c + 0) * 68 + key] = v.x; Kt[(c + 1) * 68 + key] = v.y;
        Kt[(c + 2) * 68 + key] = v.z; Kt[(c + 3) * 68 + key] = v.w;
    }
    __syncthreads();

    u64 acc[8][2];
    #pragma unroll
    for (int i = 0; i < 8; i++) { acc[i][0] = 0ull; acc[i][1] = 0ull; }

    #pragma unroll 8
    for (int dd = 0; dd < HD; dd++) {
        u64 b0 = *(const u64*)&Kt[dd * 68 + 2 * tx];
        u64 b1 = *(const u64*)&Kt[dd * 68 + 32 + 2 * tx];
        #pragma unroll
        for (int r = 0; r < 8; r++) {
            u64 ap = pack2(Qs[(ty * 8 + r) * 68 + dd]);
            fma2(acc[r][0], ap, b0);
            fma2(acc[r][1], ap, b1);
        }
    }

    float* Ebase = out + CTX_SIZE + ((size_t)bh * SEQ + qb * 128) * SEQ + kb * 64;
    #pragma unroll
    for (int r = 0; r < 8; r++) {
        int row = ty * 8 + r;
        float s0, s1, s2, s3;
        unpack2(acc[r][0], s0, s1);
        unpack2(acc[r][1], s2, s3);
        float e0 = fexp(s0 * 0.125f), e1 = fexp(s1 * 0.125f);
        float e2 = fexp(s2 * 0.125f), e3 = fexp(s3 * 0.125f);
        *(float2*)&Ebase[(size_t)row * SEQ + 2 * tx]      = make_float2(e0, e1);
        *(float2*)&Ebase[(size_t)row * SEQ + 32 + 2 * tx] = make_float2(e2, e3);
        float rs = (e0 + e1) + (e2 + e3);
        #pragma unroll
        for (int o = 8; o > 0; o >>= 1)
            rs += __shfl_xor_sync(0xffffffffu, rs, o, 16);
        if (tx == 0)
            atomicAdd(&g_rsum[(size_t)bh * SEQ + qb * 128 + row], rs);
    }
}

// ---------------------------------------------------------------------------
// K3: ctx.  Reads RAW E via cp.async (double-buffered), writes normalized
// probs from smem, accumulates E·V with d-PAIRED FFMA2 (V natural layout,
// acc[8][2] u64), rinv applied at epilogue. Tile 128q x 64d, 32 key-stages.
// ---------------------------------------------------------------------------
#define ESZ (128 * 68)   // 8704 floats / stage
#define VSZ (64 * 68)    // 4352 floats / stage
#define CT_SMEM ((2 * ESZ + 2 * VSZ) * 4)   // 104448 B

__global__ __launch_bounds__(256, 2) void ctx_kernel(float* __restrict__ out)
{
    extern __shared__ float sm[];
    __shared__ float rinv_s[128];
    const unsigned smb = (unsigned)__cvta_generic_to_shared(sm);

    const int qb = blockIdx.x;   // 0..15
    const int bh = blockIdx.y;   // 0..31
    const int batch = bh >> 4;
    const int h = bh & 15;
    const int tid = threadIdx.x;
    const int ty = tid >> 4;
    const int tx = tid & 15;

    if (tid < 128)
        rinv_s[tid] = 1.0f / g_rsum[(size_t)bh * SEQ + qb * 128 + tid];

    float* Erow = out + CTX_SIZE + ((size_t)bh * SEQ + qb * 128) * SEQ;
    const float* Vp = g_v + (size_t)bh * SEQ * HD;

    auto load_stage = [&](int s, int k0) {
        unsigned Es = smb + (unsigned)(s * ESZ) * 4u;
        unsigned Vs = smb + (unsigned)(2 * ESZ + s * VSZ) * 4u;
        #pragma unroll
        for (int it = 0; it < 8; it++) {          // E raw: 2048 float4
            int f = tid + it * 256;
            int row = f >> 4;
            int kc = (f & 15) << 2;
            cpa16(Es + (unsigned)(row * 68 + kc) * 4u,
                  &Erow[(size_t)row * SEQ + k0 + kc]);
        }
        #pragma unroll
        for (int it = 0; it < 4; it++) {          // V: 1024 float4
            int f = tid + it * 256;
            int key = f >> 4;
            int c = (f & 15) << 2;
            cpa16(Vs + (unsigned)(key * 68 + c) * 4u,
                  &Vp[(size_t)(k0 + key) * HD + c]);
        }
    };

    u64 acc[8][2];
    #pragma unroll
    for (int i = 0; i < 8; i++) { acc[i][0] = 0ull; acc[i][1] = 0ull; }

    load_stage(0, 0);
    CPA_COMMIT();

    for (int i = 0; i < 32; i++) {
        if (i < 31) { load_stage((i + 1) & 1, (i + 1) * 64); CPA_COMMIT(); CPA_WAIT1(); }
        else        { CPA_WAIT0(); }
        __syncthreads();

        const float* Es = sm + (i & 1) * ESZ;
        const float* Vs = sm + 2 * ESZ + (i & 1) * VSZ;
        const int k0 = i * 64;

        // probs: normalize raw E from smem -> global (overlaps with compute)
        #pragma unroll
        for (int it = 0; it < 8; it++) {
            int f = tid + it * 256;
            int row = f >> 4;
            int kc = (f & 15) << 2;
            float ri = rinv_s[row];
            float4 v = *(const float4*)&Es[row * 68 + kc];
            v.x *= ri; v.y *= ri; v.z *= ri; v.w *= ri;
            *(float4*)&Erow[(size_t)row * SEQ + k0 + kc] = v;
        }

        #pragma unroll 8
        for (int kk = 0; kk < 64; kk++) {
            u64 b0 = *(const u64*)&Vs[kk * 68 + 2 * tx];
            u64 b1 = *(const u64*)&Vs[kk * 68 + 32 + 2 * tx];
            #pragma unroll
            for (int r = 0; r < 8; r++) {
                u64 ap = pack2(Es[(ty * 8 + r) * 68 + kk]);
                fma2(acc[r][0], ap, b0);
                fma2(acc[r][1], ap, b1);
            }
        }
        __syncthreads();
    }

    // ctx out [b][s][h*64+d], scaled by rinv at epilogue
    #pragma unroll
    for (int r = 0; r < 8; r++) {
        int row = ty * 8 + r;
        float ri = rinv_s[row];
        int s = qb * 128 + row;
        float* p = out + ((size_t)batch * SEQ + s) * HIDDEN + h * HD;
        float x0, x1, x2, x3;
        unpack2(acc[r][0], x0, x1);
        unpack2(acc[r][1], x2, x3);
        *(float2*)&p[2 * tx]      = make_float2(x0 * ri, x1 * ri);
        *(float2*)&p[32 + 2 * tx] = make_float2(x2 * ri, x3 * ri);
    }
}

// ---------------------------------------------------------------------------
extern "C" void kernel_launch(void* const* d_in, const int* in_sizes, int n_in,
                              void* d_out, int out_size)
{
    const float* X  = (const float*)d_in[0];
    const float* Wq = (const float*)d_in[1];
    const float* bq = (const float*)d_in[2];
    const float* Wk = (const float*)d_in[3];
    const float* bk = (const float*)d_in[4];
    const float* Wv = (const float*)d_in[5];
    const float* bv = (const float*)d_in[6];
    float* out = (float*)d_out;

    zero_rsum_kernel<<<BH * SEQ / 256, 256>>>();

    dim3 g1(HIDDEN / 32, M_TOTAL / 128, 3);
    qkv_kernel<<<g1, 256>>>(X, Wq, bq, Wk, bk, Wv, bv);

    cudaFuncSetAttribute(scores_kernel,
                         cudaFuncAttributeMaxDynamicSharedMemorySize, SC_SMEM);
    dim3 g2(SEQ / 64, SEQ / 128, BH);
    scores_kernel<<<g2, 256, SC_SMEM>>>(out);

    cudaFuncSetAttribute(ctx_kernel,
                         cudaFuncAttributeMaxDynamicSharedMemorySize, CT_SMEM);
    dim3 g3(SEQ / 128, BH);
    ctx_kernel<<<g3, 256, CT_SMEM>>>(out);
}